// round 10
// baseline (speedup 1.0000x reference)
#include <cuda_runtime.h>
#include <cstdint>

// StateDecoder: out[b, r, c] = (x[b, c] >> r) & 1 as float32.
// B = 2048, C = 2048, R = 32. 16 MiB in, 512 MiB out -> HBM write-bound.
//
// R10: output-centric mapping. Thread o writes exactly out4[o] (one STG.128),
// so the grid-wide store pattern is a single dense linear sweep of the whole
// 512 MiB output in launch order — the friendliest stream for the DRAM write
// scheduler. Input word x4[b,j] is re-read by the 32 r-planes: 1 DRAM read +
// 31 L2 hits (input is tiny vs L2).

#define BATCH 2048
#define NUM_CANDIDATES 2048
#define NUM_REPLICAS 32

__device__ __forceinline__ float4 bits_to_f4(int4 v, int r) {
    // bit -> 0x00000000 or 0x3F800000 (1.0f) without I2F
    unsigned f0 = (0u - (((unsigned)v.x >> r) & 1u)) & 0x3F800000u;
    unsigned f1 = (0u - (((unsigned)v.y >> r) & 1u)) & 0x3F800000u;
    unsigned f2 = (0u - (((unsigned)v.z >> r) & 1u)) & 0x3F800000u;
    unsigned f3 = (0u - (((unsigned)v.w >> r) & 1u)) & 0x3F800000u;
    float4 f;
    f.x = __uint_as_float(f0);
    f.y = __uint_as_float(f1);
    f.z = __uint_as_float(f2);
    f.w = __uint_as_float(f3);
    return f;
}

__global__ __launch_bounds__(256) void state_decoder_kernel(
    const int4* __restrict__ x4,   // [B * C/4]
    float4* __restrict__ out4      // [B * R * C/4] = [B*R*512]
) {
    constexpr int C4 = NUM_CANDIDATES / 4;            // 512

    const unsigned o = blockIdx.x * 256u + threadIdx.x;  // linear out4 index
    const unsigned j = o & (C4 - 1);                     // o % 512
    const unsigned r = (o >> 9) & (NUM_REPLICAS - 1);    // (o/512) % 32
    const unsigned b = o >> 14;                          // o / 16384

    const int4 v = __ldg(x4 + (size_t)b * C4 + j);

    out4[o] = bits_to_f4(v, (int)r);
}

extern "C" void kernel_launch(void* const* d_in, const int* in_sizes, int n_in,
                              void* d_out, int out_size) {
    const int4* x4 = (const int4*)d_in[0];
    float4* out4 = (float4*)d_out;

    constexpr unsigned total = BATCH * NUM_REPLICAS * (NUM_CANDIDATES / 4);  // 33,554,432
    state_decoder_kernel<<<total / 256, 256>>>(x4, out4);
}

// round 11
// speedup vs baseline: 1.4727x; 1.4727x over previous
#include <cuda_runtime.h>
#include <cstdint>

// StateDecoder: out[b, r, c] = (x[b, c] >> r) & 1 as float32.
// B = 2048, C = 2048, R = 32. 16 MiB in, 512 MiB out -> HBM write-bound
// (~6.0 TB/s measured pure-write ceiling; 75% DRAM busy is the wall).
//
// Final-matrix cell: the best-profiled access shape (grid 4096 x 256, one
// int4 per thread, 32 strided STG.128 per thread amortizing one load) with
// the store policy that produced the best timed result (__stcs evict-first,
// write-once stream -> drain L2 early, no dead lines held across replays).

#define BATCH 2048
#define NUM_CANDIDATES 2048
#define NUM_REPLICAS 32

__device__ __forceinline__ float4 bits_to_f4(int4 v, int r) {
    // bit -> 0x00000000 or 0x3F800000 (1.0f) without I2F
    unsigned f0 = (0u - (((unsigned)v.x >> r) & 1u)) & 0x3F800000u;
    unsigned f1 = (0u - (((unsigned)v.y >> r) & 1u)) & 0x3F800000u;
    unsigned f2 = (0u - (((unsigned)v.z >> r) & 1u)) & 0x3F800000u;
    unsigned f3 = (0u - (((unsigned)v.w >> r) & 1u)) & 0x3F800000u;
    float4 f;
    f.x = __uint_as_float(f0);
    f.y = __uint_as_float(f1);
    f.z = __uint_as_float(f2);
    f.w = __uint_as_float(f3);
    return f;
}

__global__ __launch_bounds__(256) void state_decoder_kernel(
    const int4* __restrict__ x4,   // [B * C/4]
    float4* __restrict__ out4      // [B * R * C/4]
) {
    constexpr int C4 = NUM_CANDIDATES / 4;  // 512

    const int t = blockIdx.x * blockDim.x + threadIdx.x;  // 0 .. B*C4-1
    const int b = t / C4;
    const int j = t % C4;

    const int4 v = x4[t];

    float4* dst = out4 + (size_t)b * (NUM_REPLICAS * C4) + j;

    #pragma unroll
    for (int r = 0; r < NUM_REPLICAS; ++r) {
        __stcs(dst + (size_t)r * C4, bits_to_f4(v, r));
    }
}

extern "C" void kernel_launch(void* const* d_in, const int* in_sizes, int n_in,
                              void* d_out, int out_size) {
    const int4* x4 = (const int4*)d_in[0];
    float4* out4 = (float4*)d_out;

    constexpr int total_threads = BATCH * (NUM_CANDIDATES / 4);  // 1,048,576
    state_decoder_kernel<<<total_threads / 256, 256>>>(x4, out4);
}

// round 12
// speedup vs baseline: 1.4934x; 1.0140x over previous
#include <cuda_runtime.h>
#include <cstdint>

// StateDecoder: out[b, r, c] = (x[b, c] >> r) & 1 as float32.
// B = 2048, C = 2048, R = 32. 16 MiB in, 512 MiB out -> HBM write-bound.
//
// Winning shape (R11): flat grid 4096 x 256, one int4 per thread, 32 strided
// STG.128 per thread, __stcs evict-first stores (write-once stream; best
// timed-loop behavior). R12 adds the last byte-saver: input loaded with an
// L2 evict_last hint so the 16 MiB input survives the write sweep and stays
// L2-resident across graph replays (stcs stores leave L2 capacity free).

#define BATCH 2048
#define NUM_CANDIDATES 2048
#define NUM_REPLICAS 32

__device__ __forceinline__ float4 bits_to_f4(int4 v, int r) {
    // bit -> 0x00000000 or 0x3F800000 (1.0f) without I2F
    unsigned f0 = (0u - (((unsigned)v.x >> r) & 1u)) & 0x3F800000u;
    unsigned f1 = (0u - (((unsigned)v.y >> r) & 1u)) & 0x3F800000u;
    unsigned f2 = (0u - (((unsigned)v.z >> r) & 1u)) & 0x3F800000u;
    unsigned f3 = (0u - (((unsigned)v.w >> r) & 1u)) & 0x3F800000u;
    float4 f;
    f.x = __uint_as_float(f0);
    f.y = __uint_as_float(f1);
    f.z = __uint_as_float(f2);
    f.w = __uint_as_float(f3);
    return f;
}

__global__ __launch_bounds__(256) void state_decoder_kernel(
    const int4* __restrict__ x4,   // [B * C/4]
    float4* __restrict__ out4      // [B * R * C/4]
) {
    constexpr int C4 = NUM_CANDIDATES / 4;  // 512

    const int t = blockIdx.x * blockDim.x + threadIdx.x;  // 0 .. B*C4-1
    const int b = t / C4;
    const int j = t % C4;

    // Input load with evict_last policy: keep the 16 MiB input L2-resident
    // across graph replays (clean lines; no writeback cost).
    uint64_t pol;
    asm("createpolicy.fractional.L2::evict_last.b64 %0, 1.0;" : "=l"(pol));
    int4 v;
    asm volatile("ld.global.nc.L2::cache_hint.v4.b32 {%0, %1, %2, %3}, [%4], %5;"
                 : "=r"(v.x), "=r"(v.y), "=r"(v.z), "=r"(v.w)
                 : "l"(x4 + t), "l"(pol));

    float4* dst = out4 + (size_t)b * (NUM_REPLICAS * C4) + j;

    #pragma unroll
    for (int r = 0; r < NUM_REPLICAS; ++r) {
        __stcs(dst + (size_t)r * C4, bits_to_f4(v, r));
    }
}

extern "C" void kernel_launch(void* const* d_in, const int* in_sizes, int n_in,
                              void* d_out, int out_size) {
    const int4* x4 = (const int4*)d_in[0];
    float4* out4 = (float4*)d_out;

    constexpr int total_threads = BATCH * (NUM_CANDIDATES / 4);  // 1,048,576
    state_decoder_kernel<<<total_threads / 256, 256>>>(x4, out4);
}